// round 1
// baseline (speedup 1.0000x reference)
#include <cuda_runtime.h>

#define T_LEN 1024
#define S_LEN 1024
#define BSZ 4
#define EMB 1024
#define NH 16
#define HD 64
#define BH (BSZ*NH)   // 64

// ---------------- scratch (device globals; no allocations allowed) ----------
__device__ float g_q[BH * T_LEN * HD];              // [b,h,t,d] scaled q
__device__ float g_k[BH * S_LEN * HD];              // [b,h,s,d]
__device__ float g_v[BH * S_LEN * HD];              // [b,h,s,d]
__device__ float g_sc[(size_t)BH * T_LEN * S_LEN];  // scores -> probs in place (256MB)
__device__ float g_ctx[BH * T_LEN * HD];            // [b,h,t,d]
__device__ float g_ctx2[T_LEN * BSZ * EMB];         // [t,b,e]

// ---------------------------------------------------------------------------
// Generic NT GEMM: C[m][n] = sum_k A[m*lda+k] * B[n*ldb+k]
// 128x128 tile, 256 threads, 8x8 per thread, k-chunk 8.
// mode 0: Q projection  (A=query,  B=Wq)      -> g_q (bias, *0.125, remap)
// mode 1: KV projection (A=key,    B=Wkv)     -> g_k/g_v (bias, remap)
// mode 2: scores        (A=g_q[z], B=g_k[z])  -> g_sc[z]
// mode 3: out proj      (A=g_ctx2, B=Wout)    -> Cout (+bias)
// ---------------------------------------------------------------------------
__global__ __launch_bounds__(256, 2)
void gemm_nt(const float* __restrict__ Ain, int lda,
             const float* __restrict__ Bin, int ldb,
             const float* __restrict__ bias,
             float* __restrict__ Cout,
             int K, int mode)
{
    int z = blockIdx.z;
    const float* A = Ain;
    const float* B = Bin;
    if (mode == 2) {
        A = g_q + (size_t)z * (T_LEN * HD);
        B = g_k + (size_t)z * (S_LEN * HD);
    } else if (mode == 3) {
        A = g_ctx2;
    }

    __shared__ float As[8][128];
    __shared__ float Bs[8][128];

    int tid = threadIdx.x;
    int tx = tid & 15;        // n-direction (8 cols each)
    int ty = tid >> 4;        // m-direction (8 rows each)
    int m0 = blockIdx.y * 128;
    int n0 = blockIdx.x * 128;

    // gmem load mapping: 2 threads per tile row, float4 each
    int lr = tid >> 1;          // row in tile 0..127
    int lk = (tid & 1) * 4;     // k offset 0 or 4

    float c[8][8] = {};

    for (int k0 = 0; k0 < K; k0 += 8) {
        float4 av = *(const float4*)(A + (size_t)(m0 + lr) * lda + k0 + lk);
        float4 bv = *(const float4*)(B + (size_t)(n0 + lr) * ldb + k0 + lk);
        __syncthreads();
        As[lk + 0][lr] = av.x; As[lk + 1][lr] = av.y;
        As[lk + 2][lr] = av.z; As[lk + 3][lr] = av.w;
        Bs[lk + 0][lr] = bv.x; Bs[lk + 1][lr] = bv.y;
        Bs[lk + 2][lr] = bv.z; Bs[lk + 3][lr] = bv.w;
        __syncthreads();
        #pragma unroll
        for (int kk = 0; kk < 8; kk++) {
            float4 a0 = *(const float4*)&As[kk][ty * 8];
            float4 a1 = *(const float4*)&As[kk][ty * 8 + 4];
            float4 b0 = *(const float4*)&Bs[kk][tx * 8];
            float4 b1 = *(const float4*)&Bs[kk][tx * 8 + 4];
            float a[8] = {a0.x, a0.y, a0.z, a0.w, a1.x, a1.y, a1.z, a1.w};
            float b[8] = {b0.x, b0.y, b0.z, b0.w, b1.x, b1.y, b1.z, b1.w};
            #pragma unroll
            for (int i = 0; i < 8; i++)
                #pragma unroll
                for (int j = 0; j < 8; j++)
                    c[i][j] += a[i] * b[j];
        }
    }

    #pragma unroll
    for (int i = 0; i < 8; i++) {
        int m = m0 + ty * 8 + i;
        #pragma unroll
        for (int j = 0; j < 8; j++) {
            int f = n0 + tx * 8 + j;
            float v = c[i][j];
            if (mode == 0) {
                int t = m >> 2, b = m & 3;
                int h = f >> 6, d = f & 63;
                g_q[(size_t)(((b << 4) + h) * T_LEN + t) * HD + d] =
                    (v + bias[f]) * 0.125f;
            } else if (mode == 1) {
                v += bias[f];
                int ff = f & 1023;
                int h = ff >> 6, d = ff & 63;
                int t = m >> 2, b = m & 3;
                size_t idx = (size_t)(((b << 4) + h) * S_LEN + t) * HD + d;
                if (f < 1024) g_k[idx] = v; else g_v[idx] = v;
            } else if (mode == 2) {
                g_sc[(size_t)z * T_LEN * S_LEN + (size_t)m * S_LEN + f] = v;
            } else {
                Cout[(size_t)m * EMB + f] = v + bias[f];
            }
        }
    }
}

// ---------------------------------------------------------------------------
// Softmax + hard-mask + avg_weights.
// One block per (b,t) row; loops over 16 heads; probs written in place into
// g_sc; avg accumulated in registers and written once.
// ---------------------------------------------------------------------------
__global__ __launch_bounds__(256)
void softmax_kernel(const float* __restrict__ mask, float* __restrict__ avg_out)
{
    int bt = blockIdx.x;
    int b = bt >> 10;
    int t = bt & 1023;
    int tid = threadIdx.x;

    __shared__ float red[256];

    float avg[4] = {0.f, 0.f, 0.f, 0.f};
    float mk[4];
    #pragma unroll
    for (int j = 0; j < 4; j++)
        mk[j] = mask[((size_t)b * T_LEN + t) * S_LEN + tid + j * 256];

    for (int h = 0; h < NH; h++) {
        float* row = g_sc + (size_t)((b * NH + h) * T_LEN + t) * S_LEN;
        float x[4];
        float mx = -1e30f;
        #pragma unroll
        for (int j = 0; j < 4; j++) {
            x[j] = row[tid + j * 256];
            mx = fmaxf(mx, x[j]);
        }
        red[tid] = mx; __syncthreads();
        for (int s = 128; s > 0; s >>= 1) {
            if (tid < s) red[tid] = fmaxf(red[tid], red[tid + s]);
            __syncthreads();
        }
        mx = red[0]; __syncthreads();

        float sum = 0.f;
        #pragma unroll
        for (int j = 0; j < 4; j++) { x[j] = __expf(x[j] - mx); sum += x[j]; }
        red[tid] = sum; __syncthreads();
        for (int s = 128; s > 0; s >>= 1) {
            if (tid < s) red[tid] += red[tid + s];
            __syncthreads();
        }
        float inv = 1.f / red[0]; __syncthreads();

        #pragma unroll
        for (int j = 0; j < 4; j++) {
            float p = x[j] * inv * mk[j];
            row[tid + j * 256] = p;
            avg[j] += p;
        }
    }
    #pragma unroll
    for (int j = 0; j < 4; j++)
        avg_out[((size_t)b * T_LEN + t) * S_LEN + tid + j * 256] =
            avg[j] * (1.0f / NH);
}

// ---------------------------------------------------------------------------
// PV GEMM (NN): ctx[z][t][d] = sum_s P[z][t][s] * V[z][s][d]
// 128(t) x 64(d) tile, 256 threads, 8x4 per thread, k-chunk 16.
// ---------------------------------------------------------------------------
__global__ __launch_bounds__(256, 2)
void pv_kernel()
{
    int z = blockIdx.z;
    int t0 = blockIdx.y * 128;
    const float* P = g_sc + (size_t)z * T_LEN * S_LEN;
    const float* V = g_v + (size_t)z * S_LEN * HD;

    __shared__ float Ps[128][17];
    __shared__ float Vs[16][64];

    int tid = threadIdx.x;
    int tx = tid & 15;     // d: 4 each
    int ty = tid >> 4;     // t: 8 each

    int plr = tid >> 1;            // 0..127 (t row)
    int plk = (tid & 1) * 8;       // 0 or 8
    int vlr = tid >> 4;            // 0..15  (k row)
    int vlc = (tid & 15) * 4;      // d col

    float c[8][4] = {};

    for (int k0 = 0; k0 < S_LEN; k0 += 16) {
        float4 p0 = *(const float4*)(P + (size_t)(t0 + plr) * S_LEN + k0 + plk);
        float4 p1 = *(const float4*)(P + (size_t)(t0 + plr) * S_LEN + k0 + plk + 4);
        float4 vv = *(const float4*)(V + (size_t)(k0 + vlr) * HD + vlc);
        __syncthreads();
        Ps[plr][plk + 0] = p0.x; Ps[plr][plk + 1] = p0.y;
        Ps[plr][plk + 2] = p0.z; Ps[plr][plk + 3] = p0.w;
        Ps[plr][plk + 4] = p1.x; Ps[plr][plk + 5] = p1.y;
        Ps[plr][plk + 6] = p1.z; Ps[plr][plk + 7] = p1.w;
        *(float4*)&Vs[vlr][vlc] = vv;
        __syncthreads();
        #pragma unroll
        for (int kk = 0; kk < 16; kk++) {
            float4 bv = *(const float4*)&Vs[kk][tx * 4];
            #pragma unroll
            for (int i = 0; i < 8; i++) {
                float a = Ps[ty * 8 + i][kk];
                c[i][0] += a * bv.x; c[i][1] += a * bv.y;
                c[i][2] += a * bv.z; c[i][3] += a * bv.w;
            }
        }
    }

    #pragma unroll
    for (int i = 0; i < 8; i++) {
        int t = t0 + ty * 8 + i;
        #pragma unroll
        for (int j = 0; j < 4; j++)
            g_ctx[((size_t)z * T_LEN + t) * HD + tx * 4 + j] = c[i][j];
    }
}

// ctx[b,h,t,d] -> ctx2[(t*B+b)*E + h*64+d]
__global__ void repack_ctx()
{
    int idx = blockIdx.x * 256 + threadIdx.x;
    int e = idx & 1023;
    int m = idx >> 10;
    int t = m >> 2, b = m & 3;
    int h = e >> 6, d = e & 63;
    g_ctx2[idx] = g_ctx[(size_t)(((b << 4) + h) * T_LEN + t) * HD + d];
}

// ---------------------------------------------------------------------------
extern "C" void kernel_launch(void* const* d_in, const int* in_sizes, int n_in,
                              void* d_out, int out_size)
{
    const float* query = (const float*)d_in[0];
    const float* key   = (const float*)d_in[1];
    const float* mask  = (const float*)d_in[2];
    const float* w_in  = (const float*)d_in[3];
    const float* b_in  = (const float*)d_in[4];
    const float* w_out = (const float*)d_in[5];
    const float* b_out = (const float*)d_in[6];
    float* out = (float*)d_out;                         // [t][b][e] (4M floats)
    float* avg = out + (size_t)T_LEN * BSZ * EMB;       // [b][t][s] (4M floats)

    dim3 blk(256);

    // 1) Q projection: M=4096(t,b), N=1024, K=1024
    gemm_nt<<<dim3(8, 32, 1), blk>>>(query, EMB, w_in, EMB, b_in, nullptr, EMB, 0);
    // 2) KV projection: N=2048
    gemm_nt<<<dim3(16, 32, 1), blk>>>(key, EMB, w_in + EMB * EMB, EMB,
                                      b_in + EMB, nullptr, EMB, 1);
    // 3) scores: 64 batches of 1024x1024x64
    gemm_nt<<<dim3(8, 8, BH), blk>>>(nullptr, HD, nullptr, HD, nullptr, nullptr, HD, 2);
    // 4) softmax + mask + avg
    softmax_kernel<<<BSZ * T_LEN, 256>>>(mask, avg);
    // 5) P @ V
    pv_kernel<<<dim3(1, 8, BH), blk>>>();
    // 6) repack ctx to [t,b,e]
    repack_ctx<<<(T_LEN * BSZ * EMB) / 256, 256>>>();
    // 7) output projection -> d_out
    gemm_nt<<<dim3(8, 32, 1), blk>>>(nullptr, EMB, w_out, EMB, b_out, out, EMB, 3);
}

// round 3
// speedup vs baseline: 2.4740x; 2.4740x over previous
#include <cuda_runtime.h>
#include <cstdint>

#define T_LEN 1024
#define S_LEN 1024
#define BSZ 4
#define EMB 1024
#define NH 16
#define HD 64
#define BH (BSZ*NH)   // 64

// ---------------- scratch (device globals; no allocations allowed) ----------
__device__ float g_q[BH * T_LEN * HD];              // [z=(b,h), t, d] scaled q
__device__ float g_k[BH * S_LEN * HD];              // [z, s, d]
__device__ float g_vt[BH * HD * S_LEN];             // [z, d, s]  (V transposed)
__device__ float g_sc[(size_t)BH * T_LEN * S_LEN];  // scores -> probs (256MB)
__device__ float g_ctx[BH * T_LEN * HD];            // [z, t, d]
__device__ float g_ctx2[T_LEN * BSZ * EMB];         // [t, b, e]

// ============================================================================
__device__ __forceinline__ uint32_t f2tf32(float f) {
    uint32_t u;
    asm("cvt.rna.tf32.f32 %0, %1;" : "=r"(u) : "f"(f));
    return u;
}
__device__ __forceinline__ void mma16n8k8(float* c, const uint32_t* a, const uint32_t* b) {
    asm volatile(
        "mma.sync.aligned.m16n8k8.row.col.f32.tf32.tf32.f32 "
        "{%0,%1,%2,%3}, {%4,%5,%6,%7}, {%8,%9}, {%0,%1,%2,%3};"
        : "+f"(c[0]), "+f"(c[1]), "+f"(c[2]), "+f"(c[3])
        : "r"(a[0]), "r"(a[1]), "r"(a[2]), "r"(a[3]), "r"(b[0]), "r"(b[1]));
}

// ============================================================================
// tf32 mma.sync NT GEMM: C[m][n] = sum_k A[m*lda+k] * B[n*ldb+k]
// tile 128 x TN, 256 threads = 8 warps (4 in M x 2 in N), warp tile 32 x TN/2.
// BK=16, double-buffered smem, rows padded to 20 words (conflict-free frags).
// MODE 0: Q proj   -> g_q (bias, *0.125, [z,t,d] scatter)
// MODE 1: KV proj  -> g_k / g_vt (bias, scatter; V transposed)
// MODE 2: scores   -> g_sc[z]   (A=g_q[z], B=g_k[z], K=64)
// MODE 3: out proj -> Cout (+bias)
// MODE 4: PV       -> g_ctx[z]  (A=g_sc[z], B=g_vt[z], TN=64)
// ============================================================================
#define SROW 20

template<int TN, int MODE>
__global__ __launch_bounds__(256)
void gemm_mma(const float* __restrict__ Ain, int lda,
              const float* __restrict__ Bin, int ldb,
              const float* __restrict__ bias,
              float* __restrict__ Cout, int K)
{
    constexpr int FN = TN / 16;          // n-frags per warp
    __shared__ uint32_t As[2][128 * SROW];
    __shared__ uint32_t Bs[2][TN * SROW];

    const int tid = threadIdx.x;
    const int wid = tid >> 5, lane = tid & 31;
    const int wm = wid & 3, wn = wid >> 2;
    const int g = lane >> 2, t4 = lane & 3;
    const int m0 = blockIdx.y * 128;
    const int n0 = blockIdx.x * TN;
    const int z  = blockIdx.z;

    const float* A = Ain;
    const float* B = Bin;
    if (MODE == 2) { A = g_q + (size_t)z * (T_LEN * HD); B = g_k + (size_t)z * (S_LEN * HD); }
    if (MODE == 4) { A = g_sc + (size_t)z * T_LEN * S_LEN; B = g_vt + (size_t)z * (HD * S_LEN); }
    if (MODE == 3) { A = g_ctx2; }

    const int NI = K / 16;

    auto load_stage = [&](int s, int k0) {
        #pragma unroll
        for (int r = 0; r < 2; r++) {
            int f4 = tid + r * 256;               // 0..511
            int row = f4 >> 2, c4 = (f4 & 3) * 4;
            float4 v = *(const float4*)(A + (size_t)(m0 + row) * lda + k0 + c4);
            uint32_t* p = &As[s][row * SROW + c4];
            uint4 u = {f2tf32(v.x), f2tf32(v.y), f2tf32(v.z), f2tf32(v.w)};
            *(uint4*)p = u;
        }
        #pragma unroll
        for (int r = 0; r < TN / 64; r++) {
            int f4 = tid + r * 256;
            int row = f4 >> 2, c4 = (f4 & 3) * 4;
            float4 v = *(const float4*)(B + (size_t)(n0 + row) * ldb + k0 + c4);
            uint32_t* p = &Bs[s][row * SROW + c4];
            uint4 u = {f2tf32(v.x), f2tf32(v.y), f2tf32(v.z), f2tf32(v.w)};
            *(uint4*)p = u;
        }
    };

    float c[2][FN][4];
    #pragma unroll
    for (int mi = 0; mi < 2; mi++)
        #pragma unroll
        for (int ni = 0; ni < FN; ni++)
            #pragma unroll
            for (int e = 0; e < 4; e++) c[mi][ni][e] = 0.f;

    load_stage(0, 0);
    __syncthreads();

    for (int i = 0; i < NI; i++) {
        int s = i & 1;
        #pragma unroll
        for (int kk = 0; kk < 2; kk++) {
            uint32_t a[2][4], b[FN][2];
            #pragma unroll
            for (int mi = 0; mi < 2; mi++) {
                int r = wm * 32 + mi * 16 + g;
                int col = kk * 8 + t4;
                a[mi][0] = As[s][r * SROW + col];
                a[mi][1] = As[s][(r + 8) * SROW + col];
                a[mi][2] = As[s][r * SROW + col + 4];
                a[mi][3] = As[s][(r + 8) * SROW + col + 4];
            }
            #pragma unroll
            for (int ni = 0; ni < FN; ni++) {
                int rn = wn * (TN / 2) + ni * 8 + g;
                int col = kk * 8 + t4;
                b[ni][0] = Bs[s][rn * SROW + col];
                b[ni][1] = Bs[s][rn * SROW + col + 4];
            }
            #pragma unroll
            for (int mi = 0; mi < 2; mi++)
                #pragma unroll
                for (int ni = 0; ni < FN; ni++)
                    mma16n8k8(c[mi][ni], a[mi], b[ni]);
        }
        if (i + 1 < NI) {
            load_stage(s ^ 1, (i + 1) * 16);
            __syncthreads();
        }
    }

    // epilogue
    #pragma unroll
    for (int mi = 0; mi < 2; mi++) {
        #pragma unroll
        for (int ni = 0; ni < FN; ni++) {
            #pragma unroll
            for (int e = 0; e < 4; e++) {
                int row = m0 + wm * 32 + mi * 16 + g + ((e >= 2) ? 8 : 0);
                int col = n0 + wn * (TN / 2) + ni * 8 + t4 * 2 + (e & 1);
                float v = c[mi][ni][e];
                if (MODE == 0) {
                    int t = row >> 2, b = row & 3;
                    int h = col >> 6, d = col & 63;
                    g_q[(size_t)(((b << 4) + h) * T_LEN + t) * HD + d] =
                        (v + bias[col]) * 0.125f;
                } else if (MODE == 1) {
                    v += bias[col];
                    int ff = col & 1023;
                    int h = ff >> 6, d = ff & 63;
                    int t = row >> 2, b = row & 3;
                    int zz = (b << 4) + h;
                    if (col < 1024)
                        g_k[(size_t)(zz * S_LEN + t) * HD + d] = v;
                    else
                        g_vt[(size_t)(zz * HD + d) * S_LEN + t] = v;
                } else if (MODE == 2) {
                    g_sc[(size_t)z * T_LEN * S_LEN + (size_t)row * S_LEN + col] = v;
                } else if (MODE == 3) {
                    Cout[(size_t)row * EMB + col] = v + bias[col];
                } else {
                    g_ctx[(size_t)(z * T_LEN + row) * HD + col] = v;
                }
            }
        }
    }
}

// ---------------------------------------------------------------------------
// Softmax + hard-mask + avg_weights
// ---------------------------------------------------------------------------
__global__ __launch_bounds__(256)
void softmax_kernel(const float* __restrict__ mask, float* __restrict__ avg_out)
{
    int bt = blockIdx.x;
    int b = bt >> 10;
    int t = bt & 1023;
    int tid = threadIdx.x;

    __shared__ float red[256];

    float avg[4] = {0.f, 0.f, 0.f, 0.f};
    float mk[4];
    #pragma unroll
    for (int j = 0; j < 4; j++)
        mk[j] = mask[((size_t)b * T_LEN + t) * S_LEN + tid + j * 256];

    for (int h = 0; h < NH; h++) {
        float* row = g_sc + (size_t)((b * NH + h) * T_LEN + t) * S_LEN;
        float x[4];
        float mx = -1e30f;
        #pragma unroll
        for (int j = 0; j < 4; j++) {
            x[j] = row[tid + j * 256];
            mx = fmaxf(mx, x[j]);
        }
        red[tid] = mx; __syncthreads();
        for (int s = 128; s > 0; s >>= 1) {
            if (tid < s) red[tid] = fmaxf(red[tid], red[tid + s]);
            __syncthreads();
        }
        mx = red[0]; __syncthreads();

        float sum = 0.f;
        #pragma unroll
        for (int j = 0; j < 4; j++) { x[j] = __expf(x[j] - mx); sum += x[j]; }
        red[tid] = sum; __syncthreads();
        for (int s = 128; s > 0; s >>= 1) {
            if (tid < s) red[tid] += red[tid + s];
            __syncthreads();
        }
        float inv = 1.f / red[0]; __syncthreads();

        #pragma unroll
        for (int j = 0; j < 4; j++) {
            float p = x[j] * inv * mk[j];
            row[tid + j * 256] = p;
            avg[j] += p;
        }
    }
    #pragma unroll
    for (int j = 0; j < 4; j++)
        avg_out[((size_t)b * T_LEN + t) * S_LEN + tid + j * 256] =
            avg[j] * (1.0f / NH);
}

// ctx[z,t,d] -> ctx2[(t*B+b)*E + h*64+d]
__global__ void repack_ctx()
{
    int idx = blockIdx.x * 256 + threadIdx.x;
    int e = idx & 1023;
    int m = idx >> 10;
    int t = m >> 2, b = m & 3;
    int h = e >> 6, d = e & 63;
    g_ctx2[idx] = g_ctx[(size_t)(((b << 4) + h) * T_LEN + t) * HD + d];
}

// ---------------------------------------------------------------------------
extern "C" void kernel_launch(void* const* d_in, const int* in_sizes, int n_in,
                              void* d_out, int out_size)
{
    const float* query = (const float*)d_in[0];
    const float* key   = (const float*)d_in[1];
    const float* mask  = (const float*)d_in[2];
    const float* w_in  = (const float*)d_in[3];
    const float* b_in  = (const float*)d_in[4];
    const float* w_out = (const float*)d_in[5];
    const float* b_out = (const float*)d_in[6];
    float* out = (float*)d_out;                         // [t][b][e] (4M floats)
    float* avg = out + (size_t)T_LEN * BSZ * EMB;       // [b][t][s] (4M floats)

    dim3 blk(256);

    // 1) Q projection: M=4096, N=1024, K=1024
    gemm_mma<128, 0><<<dim3(8, 32, 1), blk>>>(query, EMB, w_in, EMB, b_in, nullptr, EMB);
    // 2) KV projection: N=2048
    gemm_mma<128, 1><<<dim3(16, 32, 1), blk>>>(key, EMB, w_in + EMB * EMB, EMB,
                                               b_in + EMB, nullptr, EMB);
    // 3) scores: 64 batches of 1024x1024x64
    gemm_mma<128, 2><<<dim3(8, 8, BH), blk>>>(nullptr, HD, nullptr, HD, nullptr, nullptr, HD);
    // 4) softmax + mask + avg
    softmax_kernel<<<BSZ * T_LEN, 256>>>(mask, avg);
    // 5) P @ V  (NT via transposed V), N=64
    gemm_mma<64, 4><<<dim3(1, 8, BH), blk>>>(nullptr, S_LEN, nullptr, S_LEN,
                                             nullptr, nullptr, S_LEN);
    // 6) repack ctx to [t,b,e]
    repack_ctx<<<(T_LEN * BSZ * EMB) / 256, 256>>>();
    // 7) output projection -> d_out
    gemm_mma<128, 3><<<dim3(8, 32, 1), blk>>>(nullptr, EMB, w_out, EMB, b_out, out, EMB);
}